// round 9
// baseline (speedup 1.0000x reference)
#include <cuda_runtime.h>

#define BB 32
#define NN 256
#define DD 128
#define NEG_MASK (-9000000.0f)
#define LEAK 0.2f

// Scratch for masked relation scores (allowed: __device__ globals)
__device__ float g_s1[BB * NN * NN];
__device__ float g_s2[BB * NN * NN];

// ---------------------------------------------------------------------------
// f32x2 packed-math helpers
// ---------------------------------------------------------------------------
typedef unsigned long long ull;

__device__ __forceinline__ ull fma2(ull a, ull b, ull c) {
    ull d;
    asm("fma.rn.f32x2 %0, %1, %2, %3;" : "=l"(d) : "l"(a), "l"(b), "l"(c));
    return d;
}
__device__ __forceinline__ ull pack2(float lo, float hi) {
    ull d;
    asm("mov.b64 %0, {%1, %2};" : "=l"(d) : "f"(lo), "f"(hi));
    return d;
}
__device__ __forceinline__ void unpack2(ull v, float& lo, float& hi) {
    asm("mov.b64 {%0, %1}, %2;" : "=f"(lo), "=f"(hi) : "l"(v));
}

// ---------------------------------------------------------------------------
// Kernel A: masked gated relation scores (unchanged — verified R5..R8).
// ---------------------------------------------------------------------------
#define TI 8
#define P4 33
#define HIW_F4 (TI * 4 * (DD / 4))
#define HJ_F4 (128 * P4)
#define SMEM_BYTES ((HIW_F4 + HJ_F4) * 16)

extern __shared__ float4 sm4[];

__global__ __launch_bounds__(256, 2) void scores_kernel(
    const float* __restrict__ sem, const float* __restrict__ strv,
    const int* __restrict__ adj,
    const float* __restrict__ aw, const float* __restrict__ swt)
{
    const int b = blockIdx.y;
    const int i0 = blockIdx.x * TI;
    const int tid = threadIdx.x;

    float4* sm_hiw4 = sm4;
    float4* sm_hj4 = sm4 + HIW_F4;

    const int w8 = tid >> 5, lane = tid & 31;
    const int jgrp = w8 & 3, ibase = (w8 >> 2) * 4;
    const int jloc = jgrp * 32 + lane;

    for (int e = 0; e < 2; e++) {
        const float* h = e ? strv : sem;
        const float* wmat = e ? swt : aw;
        float* gs = e ? g_s2 : g_s1;

        __syncthreads();
        for (int idx = tid; idx < TI * 4 * DD; idx += 256) {
            int d = idx & 127;
            int r = (idx >> 7) & 3;
            int i = idx >> 9;
            ((float*)sm_hiw4)[(i * 128 + ((d >> 2) << 2) + r) * 4 + (d & 3)] =
                h[((b * NN) + i0 + i) * DD + d] * wmat[r * DD + d];
        }

        for (int c = 0; c < 2; c++) {
            __syncthreads();
            for (int idx = tid; idx < 128 * (DD / 4); idx += 256) {
                int d4 = idx & 31;
                int jl = idx >> 5;
                sm_hj4[jl * P4 + d4] =
                    ((const float4*)(h + ((b * NN) + c * 128 + jl) * DD))[d4];
            }
            __syncthreads();

            const int j = c * 128 + jloc;

            int msk[4], off[4];
#pragma unroll
            for (int ii = 0; ii < 4; ii++) {
                int a = adj[((b * NN) + i0 + ibase + ii) * NN + j];
                msk[ii] = a;
                int r = a > 0 ? a - 1 : 0;
                off[ii] = (ibase + ii) * 128 + r;
            }

            ull acc[4];
#pragma unroll
            for (int ii = 0; ii < 4; ii++) acc[ii] = 0ull;

            const ulonglong2* hiw2 = (const ulonglong2*)sm_hiw4;
            const ulonglong2* hj2 = (const ulonglong2*)sm_hj4 + jloc * P4;

#pragma unroll 8
            for (int d4 = 0; d4 < 32; d4++) {
                ulonglong2 hv = hj2[d4];
                int dbase = d4 << 2;
#pragma unroll
                for (int ii = 0; ii < 4; ii++) {
                    ulonglong2 wv = hiw2[off[ii] + dbase];
                    acc[ii] = fma2(wv.x, hv.x, acc[ii]);
                    acc[ii] = fma2(wv.y, hv.y, acc[ii]);
                }
            }

#pragma unroll
            for (int ii = 0; ii < 4; ii++) {
                float lo, hi;
                unpack2(acc[ii], lo, hi);
                float v = lo + hi;
                v = msk[ii] > 0 ? (v >= 0.f ? v : LEAK * v) : NEG_MASK;
                gs[((b * NN) + i0 + ibase + ii) * NN + j] = v;
            }
        }
    }
}

// ---------------------------------------------------------------------------
// Kernel B v5: register-sparse entmax, single-wave occupancy.
// 2 rows/warp, 16-lane groups. No dense smem buffer: overflow fallback
// streams from gmem (never taken statistically; exact when taken).
// grid (NN/16, BB) = 512 CTAs x 256 threads, 4 CTAs/SM -> one wave.
// ---------------------------------------------------------------------------
#define CROWS2 16
#define CAP1 96
#define CAP2 32
#define NL1 (CAP1 / 16)   // 6 register slots per lane
#define NL2 (CAP2 / 16)   // 2
#define LST1 112          // float stride, %32==16 -> conflict-free dual groups
#define LST2 48

__device__ __forceinline__ float gsum16(float v) {
#pragma unroll
    for (int o = 1; o < 16; o <<= 1) v += __shfl_xor_sync(0xffffffffu, v, o);
    return v;
}
__device__ __forceinline__ float gmax16(float v) {
#pragma unroll
    for (int o = 1; o < 16; o <<= 1) v = fmaxf(v, __shfl_xor_sync(0xffffffffu, v, o));
    return v;
}

template <int MODE>
__device__ __forceinline__ float pfm(float t, float inv) {
    // t is already max(z, 0)
    if (MODE == 2) return t * t;     // alpha = 1.5
    if (MODE == 1) return t;         // alpha = 2.0
    return __powf(t, inv);           // generic
}

template <int MODE, int NL>
__device__ __forceinline__ float evalRegs(const float* __restrict__ L,
                                          float tau, float inv) {
    float a = 0.f;
#pragma unroll
    for (int i = 0; i < NL; i++)
        a += pfm<MODE>(fmaxf(L[i] - tau, 0.f), inv);
    return a;
}

// Fallback: stream the row from gmem (16-lane strided), recompute Xs each time
// (FMUL.RN, deterministic — identical value every evaluation).
template <int MODE>
__device__ float evalDenseG(const float* __restrict__ grow, int s,
                            float am1, float tau, float inv) {
    float a0 = 0.f, a1 = 0.f, a2 = 0.f, a3 = 0.f;
    const float4* g4 = (const float4*)grow;
#pragma unroll 1
    for (int t = 0; t < 4; t++) {
        float4 v = g4[s + 16 * t];
        a0 += pfm<MODE>(fmaxf(__fmul_rn(v.x, am1) - tau, 0.f), inv);
        a1 += pfm<MODE>(fmaxf(__fmul_rn(v.y, am1) - tau, 0.f), inv);
        a2 += pfm<MODE>(fmaxf(__fmul_rn(v.z, am1) - tau, 0.f), inv);
        a3 += pfm<MODE>(fmaxf(__fmul_rn(v.w, am1) - tau, 0.f), inv);
    }
    return (a0 + a1) + (a2 + a3);
}

template <int M1, int M2>
__device__ void cwork(const float* __restrict__ sem, float* __restrict__ out,
                      int b, int i0, int tid,
                      float am1_1, float am1_2, float inv1, float inv2,
                      float* sV1, unsigned char* sI1, float* sV2,
                      int* sN1, float* sScale)
{
    const int w = tid >> 5, lane = tid & 31;
    const int g = lane >> 4, s = lane & 15;
    const int r = 2 * w + g;
    const int row = i0 + r;

    float* sList1 = sV1 + r * LST1;
    unsigned char* sIdx1 = sI1 + r * LST1;
    float* sList2 = sV2 + r * LST2;

    const float* g1row = g_s1 + ((b * NN) + row) * NN;
    const float* g2row = g_s2 + ((b * NN) + row) * NN;
    const float4* x1g = (const float4*)g1row;
    const float4* x2g = (const float4*)g2row;

    // Load + scale (FMUL.RN as reference); X regs die after compaction.
    float4 X1[4], X2[4];
    float mx1 = -3.4e38f, mx2 = -3.4e38f;
#pragma unroll
    for (int t = 0; t < 4; t++) {
        float4 v = x1g[s + 16 * t];
        v.x *= am1_1; v.y *= am1_1; v.z *= am1_1; v.w *= am1_1;
        X1[t] = v;
        mx1 = fmaxf(mx1, fmaxf(fmaxf(v.x, v.y), fmaxf(v.z, v.w)));
        float4 u = x2g[s + 16 * t];
        u.x *= am1_2; u.y *= am1_2; u.z *= am1_2; u.w *= am1_2;
        X2[t] = u;
        mx2 = fmaxf(mx2, fmaxf(fmaxf(u.x, u.y), fmaxf(u.z, u.w)));
    }
    mx1 = gmax16(mx1);
    mx2 = gmax16(mx2);
    const float thr1 = mx1 - 1.f, thr2 = mx2 - 1.f;   // tau_lo

    // Candidate counts + one packed 16-lane inclusive scan (R7/R8-verified)
    int c1 = 0, c2 = 0;
#pragma unroll
    for (int t = 0; t < 4; t++) {
        c1 += (X1[t].x > thr1) + (X1[t].y > thr1) + (X1[t].z > thr1) + (X1[t].w > thr1);
        c2 += (X2[t].x > thr2) + (X2[t].y > thr2) + (X2[t].z > thr2) + (X2[t].w > thr2);
    }
    int incl = c1 | (c2 << 16);
#pragma unroll
    for (int o = 1; o < 16; o <<= 1) {
        int u = __shfl_up_sync(0xffffffffu, incl, o);
        if (s >= o) incl += u;
    }
    int tot = __shfl_sync(0xffffffffu, incl, (lane & 16) | 15);
    const int ntot1 = tot & 0xffff, ntot2 = tot >> 16;
    const int pfx1 = (incl & 0xffff) - c1, pfx2 = (incl >> 16) - c2;

    const bool ok1 = (M1 != 0) && (ntot1 <= CAP1);
    const bool ok2 = (M2 != 0) && (ntot2 <= CAP2);

    // Compact to smem (once), pad to cap with thr (exact zeros for tau>=thr)
    if (ok1) {
        int pos = pfx1;
#pragma unroll
        for (int t = 0; t < 4; t++) {
            int jb = 4 * (s + 16 * t);
            if (X1[t].x > thr1) { sList1[pos] = X1[t].x; sIdx1[pos] = (unsigned char)jb;       pos++; }
            if (X1[t].y > thr1) { sList1[pos] = X1[t].y; sIdx1[pos] = (unsigned char)(jb + 1); pos++; }
            if (X1[t].z > thr1) { sList1[pos] = X1[t].z; sIdx1[pos] = (unsigned char)(jb + 2); pos++; }
            if (X1[t].w > thr1) { sList1[pos] = X1[t].w; sIdx1[pos] = (unsigned char)(jb + 3); pos++; }
        }
        for (int p = ntot1 + s; p < CAP1; p += 16) { sList1[p] = thr1; sIdx1[p] = 0; }
    }
    if (ok2) {
        int pos = pfx2;
#pragma unroll
        for (int t = 0; t < 4; t++) {
            if (X2[t].x > thr2) sList2[pos++] = X2[t].x;
            if (X2[t].y > thr2) sList2[pos++] = X2[t].y;
            if (X2[t].z > thr2) sList2[pos++] = X2[t].z;
            if (X2[t].w > thr2) sList2[pos++] = X2[t].w;
        }
        for (int p = ntot2 + s; p < CAP2; p += 16) sList2[p] = thr2;
    }
    __syncwarp();

    // Reload candidates into per-lane registers (once, static unroll)
    float L1[NL1];
    int I1[NL1];
    float L2[NL2];
    if (ok1) {
#pragma unroll
        for (int i = 0; i < NL1; i++) {
            L1[i] = sList1[s + 16 * i];
            I1[i] = sIdx1[s + 16 * i];
        }
    }
    if (ok2) {
#pragma unroll
        for (int i = 0; i < NL2; i++) L2[i] = sList2[s + 16 * i];
    }

    // 30-iteration bisection (reference-faithful), register eval on hot path
    float tau1 = thr1, tau2 = thr2;
    float dm1 = 1.f - exp2f(-8.f * am1_1);
    float dm2 = 1.f - exp2f(-8.f * am1_2);

    float f1 = ok1 ? evalRegs<M1, NL1>(L1, tau1, inv1)
                   : evalDenseG<M1>(g1row, s, am1_1, tau1, inv1);
    float f2 = ok2 ? evalRegs<M2, NL2>(L2, tau2, inv2)
                   : evalDenseG<M2>(g2row, s, am1_2, tau2, inv2);
    const float flo1 = gsum16(f1) - 1.f;
    const float flo2 = gsum16(f2) - 1.f;

#pragma unroll 1
    for (int it = 0; it < 30; it++) {
        dm1 *= 0.5f;
        dm2 *= 0.5f;
        float tm1 = tau1 + dm1, tm2 = tau2 + dm2;
        float a = ok1 ? evalRegs<M1, NL1>(L1, tm1, inv1)
                      : evalDenseG<M1>(g1row, s, am1_1, tm1, inv1);
        float bs = ok2 ? evalRegs<M2, NL2>(L2, tm2, inv2)
                       : evalDenseG<M2>(g2row, s, am1_2, tm2, inv2);
        a = gsum16(a);
        bs = gsum16(bs);
        if ((a - 1.f) * flo1 >= 0.f) tau1 = tm1;
        if ((bs - 1.f) * flo2 >= 0.f) tau2 = tm2;
    }

    const float S1 = gsum16(ok1 ? evalRegs<M1, NL1>(L1, tau1, inv1)
                                : evalDenseG<M1>(g1row, s, am1_1, tau1, inv1));
    const float S2 = gsum16(ok2 ? evalRegs<M2, NL2>(L2, tau2, inv2)
                                : evalDenseG<M2>(g2row, s, am1_2, tau2, inv2));

    // wf = p1*p2 (support within list1); p2 recomputed from g_s2 (R6-verified)
    float s3p = 0.f;
    if (ok1) {
#pragma unroll
        for (int i = 0; i < NL1; i++) {
            float p1 = pfm<M1>(fmaxf(L1[i] - tau1, 0.f), inv1);
            float x2 = __fmul_rn(g2row[I1[i]], am1_2);
            float p2 = pfm<M2>(fmaxf(x2 - tau2, 0.f), inv2);
            float wf = p1 * p2;
            s3p += wf;
            sList1[s + 16 * i] = wf;   // overwrite value slot with wf (pads -> 0)
        }
    } else {
        // Overflow fallback: materialize wf into g_s1 row (raw g1 dead now)
        float* g1w = g_s1 + ((b * NN) + row) * NN;
#pragma unroll 1
        for (int t = 0; t < 16; t++) {
            int j = s + 16 * t;
            float x1 = __fmul_rn(g1w[j], am1_1);
            float x2 = __fmul_rn(g2row[j], am1_2);
            float p1 = pfm<M1>(fmaxf(x1 - tau1, 0.f), inv1);
            float p2 = pfm<M2>(fmaxf(x2 - tau2, 0.f), inv2);
            float wf = p1 * p2;
            s3p += wf;
            g1w[j] = wf;
        }
        __threadfence_block();
    }
    float s3 = gsum16(s3p);
    if (s == 0) {
        sN1[r] = ok1 ? ntot1 : -1;
        // weight = p1p2/(S1S2) / (S3/(S1S2)+1e-7) = p1p2 / (S3 + 1e-7 S1 S2)
        sScale[r] = 1.f / (s3 + 1e-7f * S1 * S2);
    }
    __syncwarp();

    // Sparse output GEMV: warp-wide per row, lane = d4.
    // Pads carry wf == 0 exactly -> loop padded count, unrolled x4.
    const ulonglong2* semb2 = (const ulonglong2*)(sem + b * NN * DD);
#pragma unroll
    for (int q = 0; q < 2; q++) {
        int rr = 2 * w + q;
        int n1 = sN1[rr];
        float sc = sScale[rr];
        const float* wfl = sV1 + rr * LST1;
        const unsigned char* jl = sI1 + rr * LST1;
        ull accA = 0ull, accB = 0ull;
        if (n1 >= 0) {
            int n1r = (n1 + 15) & ~15;
#pragma unroll 1
            for (int k = 0; k < n1r; k += 4) {
#pragma unroll
                for (int u = 0; u < 4; u++) {
                    float wf = wfl[k + u];
                    int j = jl[k + u];
                    ulonglong2 vv = semb2[j * 32 + lane];
                    ull wv = pack2(wf, wf);
                    accA = fma2(wv, vv.x, accA);
                    accB = fma2(wv, vv.y, accB);
                }
            }
        } else {
            const float* g1w = g_s1 + ((b * NN) + i0 + rr) * NN;
#pragma unroll 1
            for (int j = 0; j < NN; j++) {
                float wf = g1w[j];
                ulonglong2 vv = semb2[j * 32 + lane];
                ull wv = pack2(wf, wf);
                accA = fma2(wv, vv.x, accA);
                accB = fma2(wv, vv.y, accB);
            }
        }
        float4 o;
        unpack2(accA, o.x, o.y);
        unpack2(accB, o.z, o.w);
        o.x *= sc; o.y *= sc; o.z *= sc; o.w *= sc;
        ((float4*)out)[((b * NN) + i0 + rr) * 32 + lane] = o;
    }
}

__global__ __launch_bounds__(256, 4) void combine5_kernel(
    const float* __restrict__ sem,
    const float* __restrict__ alpha1p, const float* __restrict__ alpha2p,
    float* __restrict__ out)
{
    __shared__ float sV1[CROWS2 * LST1];          // 7168 B
    __shared__ unsigned char sI1[CROWS2 * LST1];  // 1792 B
    __shared__ float sV2[CROWS2 * LST2];          // 3072 B
    __shared__ int sN1[CROWS2];
    __shared__ float sScale[CROWS2];

    const int b = blockIdx.y, i0 = blockIdx.x * CROWS2;
    const int tid = threadIdx.x;

    float a1 = alpha1p[0], a2 = alpha2p[0];
    float am1_1 = a1 - 1.f, am1_2 = a2 - 1.f;
    float inv1 = 1.f / am1_1, inv2 = 1.f / am1_2;
    int m1 = (fabsf(a1 - 1.5f) < 1e-4f) ? 2 : ((fabsf(a1 - 2.f) < 1e-4f) ? 1 : 0);
    int m2 = (fabsf(a2 - 1.5f) < 1e-4f) ? 2 : ((fabsf(a2 - 2.f) < 1e-4f) ? 1 : 0);

    if (m1 == 2 && m2 == 1)
        cwork<2, 1>(sem, out, b, i0, tid, am1_1, am1_2, inv1, inv2,
                    sV1, sI1, sV2, sN1, sScale);
    else if (m1 == 1 && m2 == 2)
        cwork<1, 2>(sem, out, b, i0, tid, am1_1, am1_2, inv1, inv2,
                    sV1, sI1, sV2, sN1, sScale);
    else if (m1 == 2 && m2 == 2)
        cwork<2, 2>(sem, out, b, i0, tid, am1_1, am1_2, inv1, inv2,
                    sV1, sI1, sV2, sN1, sScale);
    else if (m1 == 1 && m2 == 1)
        cwork<1, 1>(sem, out, b, i0, tid, am1_1, am1_2, inv1, inv2,
                    sV1, sI1, sV2, sN1, sScale);
    else
        cwork<0, 0>(sem, out, b, i0, tid, am1_1, am1_2, inv1, inv2,
                    sV1, sI1, sV2, sN1, sScale);
}

// ---------------------------------------------------------------------------
extern "C" void kernel_launch(void* const* d_in, const int* in_sizes, int n_in,
                              void* d_out, int out_size)
{
    const float* sem  = (const float*)d_in[0];
    const float* strv = (const float*)d_in[1];
    const int*   adj  = (const int*)d_in[2];
    const float* aw   = (const float*)d_in[3];
    const float* swt  = (const float*)d_in[4];
    const float* a1   = (const float*)d_in[5];
    const float* a2   = (const float*)d_in[6];
    float* out = (float*)d_out;

    cudaFuncSetAttribute(scores_kernel,
                         cudaFuncAttributeMaxDynamicSharedMemorySize, SMEM_BYTES);

    scores_kernel<<<dim3(NN / TI, BB), 256, SMEM_BYTES>>>(
        sem, strv, adj, aw, swt);
    combine5_kernel<<<dim3(NN / CROWS2, BB), 256>>>(sem, a1, a2, out);
}

// round 10
// speedup vs baseline: 1.5394x; 1.5394x over previous
#include <cuda_runtime.h>

#define BB 32
#define NN 256
#define DD 128
#define NEG_MASK (-9000000.0f)
#define LEAK 0.2f

// Scratch for masked relation scores (allowed: __device__ globals)
__device__ float g_s1[BB * NN * NN];
__device__ float g_s2[BB * NN * NN];

// ---------------------------------------------------------------------------
// f32x2 packed-math helpers
// ---------------------------------------------------------------------------
typedef unsigned long long ull;

__device__ __forceinline__ ull fma2(ull a, ull b, ull c) {
    ull d;
    asm("fma.rn.f32x2 %0, %1, %2, %3;" : "=l"(d) : "l"(a), "l"(b), "l"(c));
    return d;
}
__device__ __forceinline__ ull pack2(float lo, float hi) {
    ull d;
    asm("mov.b64 %0, {%1, %2};" : "=l"(d) : "f"(lo), "f"(hi));
    return d;
}
__device__ __forceinline__ void unpack2(ull v, float& lo, float& hi) {
    asm("mov.b64 {%0, %1}, %2;" : "=f"(lo), "=f"(hi) : "l"(v));
}

// ---------------------------------------------------------------------------
// Kernel A: masked gated relation scores. TI=8, one embed at a time.
// Change vs R5-verified: dual accumulators per ii (halved FMA chain depth).
// ---------------------------------------------------------------------------
#define TI 8
#define P4 33
#define HIW_F4 (TI * 4 * (DD / 4))
#define HJ_F4 (128 * P4)
#define SMEM_BYTES ((HIW_F4 + HJ_F4) * 16)

extern __shared__ float4 sm4[];

__global__ __launch_bounds__(256, 2) void scores_kernel(
    const float* __restrict__ sem, const float* __restrict__ strv,
    const int* __restrict__ adj,
    const float* __restrict__ aw, const float* __restrict__ swt)
{
    const int b = blockIdx.y;
    const int i0 = blockIdx.x * TI;
    const int tid = threadIdx.x;

    float4* sm_hiw4 = sm4;
    float4* sm_hj4 = sm4 + HIW_F4;

    const int w8 = tid >> 5, lane = tid & 31;
    const int jgrp = w8 & 3, ibase = (w8 >> 2) * 4;
    const int jloc = jgrp * 32 + lane;

    for (int e = 0; e < 2; e++) {
        const float* h = e ? strv : sem;
        const float* wmat = e ? swt : aw;
        float* gs = e ? g_s2 : g_s1;

        __syncthreads();
        // Build hiw: float4 idx = i*128 + d4*4 + r, comp = d&3
        for (int idx = tid; idx < TI * 4 * DD; idx += 256) {
            int d = idx & 127;
            int r = (idx >> 7) & 3;
            int i = idx >> 9;
            ((float*)sm_hiw4)[(i * 128 + ((d >> 2) << 2) + r) * 4 + (d & 3)] =
                h[((b * NN) + i0 + i) * DD + d] * wmat[r * DD + d];
        }

        for (int c = 0; c < 2; c++) {
            __syncthreads();
            // Stage hj chunk [128 j][128 d] (coalesced)
            for (int idx = tid; idx < 128 * (DD / 4); idx += 256) {
                int d4 = idx & 31;
                int jl = idx >> 5;
                sm_hj4[jl * P4 + d4] =
                    ((const float4*)(h + ((b * NN) + c * 128 + jl) * DD))[d4];
            }
            __syncthreads();

            const int j = c * 128 + jloc;

            int msk[4], off[4];
#pragma unroll
            for (int ii = 0; ii < 4; ii++) {
                int a = adj[((b * NN) + i0 + ibase + ii) * NN + j];
                msk[ii] = a;
                int r = a > 0 ? a - 1 : 0;
                off[ii] = (ibase + ii) * 128 + r;   // 16B units
            }

            ull acc0[4], acc1[4];
#pragma unroll
            for (int ii = 0; ii < 4; ii++) { acc0[ii] = 0ull; acc1[ii] = 0ull; }

            const ulonglong2* hiw2 = (const ulonglong2*)sm_hiw4;
            const ulonglong2* hj2 = (const ulonglong2*)sm_hj4 + jloc * P4;

#pragma unroll 8
            for (int d4 = 0; d4 < 32; d4++) {
                ulonglong2 hv = hj2[d4];
                int dbase = d4 << 2;
#pragma unroll
                for (int ii = 0; ii < 4; ii++) {
                    ulonglong2 wv = hiw2[off[ii] + dbase];
                    acc0[ii] = fma2(wv.x, hv.x, acc0[ii]);   // independent
                    acc1[ii] = fma2(wv.y, hv.y, acc1[ii]);   // chains
                }
            }

#pragma unroll
            for (int ii = 0; ii < 4; ii++) {
                float l0, h0, l1, h1;
                unpack2(acc0[ii], l0, h0);
                unpack2(acc1[ii], l1, h1);
                float v = (l0 + h0) + (l1 + h1);
                v = msk[ii] > 0 ? (v >= 0.f ? v : LEAK * v) : NEG_MASK;
                gs[((b * NN) + i0 + ibase + ii) * NN + j] = v;
            }
        }
    }
}

// ---------------------------------------------------------------------------
// Kernel B: R3-measured combine (58.6us). 4 rows/warp via 8-lane groups,
// interleaved dual entmax, folded normalization, f32x2 GEMV.
// grid (N/32, B) = 256 CTAs x 256 threads.
// ---------------------------------------------------------------------------
__device__ __forceinline__ float gsum8(float v) {
#pragma unroll
    for (int o = 1; o < 8; o <<= 1) v += __shfl_xor_sync(0xffffffffu, v, o);
    return v;
}
__device__ __forceinline__ float gmax8(float v) {
#pragma unroll
    for (int o = 1; o < 8; o <<= 1) v = fmaxf(v, __shfl_xor_sync(0xffffffffu, v, o));
    return v;
}

template <int MODE>
__device__ __forceinline__ float pf(float z, float inv) {
    float t = fmaxf(z, 0.f);
    if (MODE == 2) return t * t;     // alpha = 1.5
    if (MODE == 1) return t;         // alpha = 2.0 (sparsemax)
    return __powf(t, inv);           // generic
}

template <int MODE>
__device__ __forceinline__ float psum32(const float4* X, float tau, float inv) {
    float4 a = make_float4(0.f, 0.f, 0.f, 0.f);
#pragma unroll
    for (int t = 0; t < 8; t++) {
        a.x += pf<MODE>(X[t].x - tau, inv);
        a.y += pf<MODE>(X[t].y - tau, inv);
        a.z += pf<MODE>(X[t].z - tau, inv);
        a.w += pf<MODE>(X[t].w - tau, inv);
    }
    return (a.x + a.y) + (a.z + a.w);
}

template <int M1, int M2>
__device__ __forceinline__ void entmax_pair(
    const float* __restrict__ s1row, const float* __restrict__ s2row,
    float am1_1, float am1_2, float inv1, float inv2,
    float4* __restrict__ wrow4, float* __restrict__ wscale_slot, int s)
{
    float4 X1[8], X2[8];
    float mx1 = -3.4e38f, mx2 = -3.4e38f;
#pragma unroll
    for (int t = 0; t < 8; t++) {
        float4 v = ((const float4*)s1row)[s + 8 * t];
        v.x *= am1_1; v.y *= am1_1; v.z *= am1_1; v.w *= am1_1;
        X1[t] = v;
        mx1 = fmaxf(mx1, fmaxf(fmaxf(v.x, v.y), fmaxf(v.z, v.w)));
        float4 u = ((const float4*)s2row)[s + 8 * t];
        u.x *= am1_2; u.y *= am1_2; u.z *= am1_2; u.w *= am1_2;
        X2[t] = u;
        mx2 = fmaxf(mx2, fmaxf(fmaxf(u.x, u.y), fmaxf(u.z, u.w)));
    }
    mx1 = gmax8(mx1);
    mx2 = gmax8(mx2);

    float tau1 = mx1 - 1.f, tau2 = mx2 - 1.f;
    float dm1 = 1.f - exp2f(-8.f * am1_1);
    float dm2 = 1.f - exp2f(-8.f * am1_2);

    float flo1 = gsum8(psum32<M1>(X1, tau1, inv1)) - 1.f;
    float flo2 = gsum8(psum32<M2>(X2, tau2, inv2)) - 1.f;

#pragma unroll 1
    for (int it = 0; it < 30; it++) {
        dm1 *= 0.5f;
        dm2 *= 0.5f;
        float tm1 = tau1 + dm1;
        float tm2 = tau2 + dm2;
        float ss1 = psum32<M1>(X1, tm1, inv1);
        float ss2 = psum32<M2>(X2, tm2, inv2);
        ss1 = gsum8(ss1);
        ss2 = gsum8(ss2);
        float fm1 = ss1 - 1.f;
        float fm2 = ss2 - 1.f;
        if (fm1 * flo1 >= 0.f) tau1 = tm1;
        if (fm2 * flo2 >= 0.f) tau2 = tm2;
    }

    // Final: p1, p2, raw product -> smem; partial sums for scale
    float s1 = 0.f, s2 = 0.f, s3 = 0.f;
#pragma unroll
    for (int t = 0; t < 8; t++) {
        float4 p1, p2, wf;
        p1.x = pf<M1>(X1[t].x - tau1, inv1); p2.x = pf<M2>(X2[t].x - tau2, inv2);
        p1.y = pf<M1>(X1[t].y - tau1, inv1); p2.y = pf<M2>(X2[t].y - tau2, inv2);
        p1.z = pf<M1>(X1[t].z - tau1, inv1); p2.z = pf<M2>(X2[t].z - tau2, inv2);
        p1.w = pf<M1>(X1[t].w - tau1, inv1); p2.w = pf<M2>(X2[t].w - tau2, inv2);
        wf.x = p1.x * p2.x; wf.y = p1.y * p2.y;
        wf.z = p1.z * p2.z; wf.w = p1.w * p2.w;
        s1 += (p1.x + p1.y) + (p1.z + p1.w);
        s2 += (p2.x + p2.y) + (p2.z + p2.w);
        s3 += (wf.x + wf.y) + (wf.z + wf.w);
        wrow4[s + 8 * t] = wf;
    }
    s1 = gsum8(s1);
    s2 = gsum8(s2);
    s3 = gsum8(s3);
    // weight = (p1 p2 / (S1 S2)) / (s3/(S1 S2) + 1e-7) = p1 p2 / (s3 + 1e-7 S1 S2)
    float scale = 1.f / (s3 + 1e-7f * s1 * s2);
    if (s == 0) *wscale_slot = scale;
}

__global__ __launch_bounds__(256, 2) void combine_kernel(
    const float* __restrict__ sem,
    const float* __restrict__ alpha1p, const float* __restrict__ alpha2p,
    float* __restrict__ out)
{
    __shared__ float4 wsm4[32][NN / 4];   // 32 rows x 256 weights (raw)
    __shared__ float wscale[32];

    const int b = blockIdx.y;
    const int i0 = blockIdx.x * 32;
    const int tid = threadIdx.x;
    const int w = tid >> 5, lane = tid & 31;
    const int g = lane >> 3, s = lane & 7;
    const int rowLocal = w * 4 + g;
    const int row = i0 + rowLocal;

    const float* s1row = g_s1 + ((b * NN) + row) * NN;
    const float* s2row = g_s2 + ((b * NN) + row) * NN;

    float a1 = alpha1p[0], a2 = alpha2p[0];
    float am1_1 = a1 - 1.f, am1_2 = a2 - 1.f;
    float inv1 = 1.f / am1_1, inv2 = 1.f / am1_2;

    int m1 = (fabsf(a1 - 1.5f) < 1e-4f) ? 2 : ((fabsf(a1 - 2.f) < 1e-4f) ? 1 : 0);
    int m2 = (fabsf(a2 - 1.5f) < 1e-4f) ? 2 : ((fabsf(a2 - 2.f) < 1e-4f) ? 1 : 0);

    if (m1 == 2 && m2 == 1)
        entmax_pair<2, 1>(s1row, s2row, am1_1, am1_2, inv1, inv2,
                          wsm4[rowLocal], &wscale[rowLocal], s);
    else if (m1 == 1 && m2 == 2)
        entmax_pair<1, 2>(s1row, s2row, am1_1, am1_2, inv1, inv2,
                          wsm4[rowLocal], &wscale[rowLocal], s);
    else
        entmax_pair<0, 0>(s1row, s2row, am1_1, am1_2, inv1, inv2,
                          wsm4[rowLocal], &wscale[rowLocal], s);

    __syncthreads();

    // Output GEMV: thread -> d4 = tid&31, 4 rows = (tid>>5)*4 + k  (f32x2 math)
    const int d4 = tid & 31, rbase = (tid >> 5) * 4;
    ull accA[4], accB[4];
#pragma unroll
    for (int k = 0; k < 4; k++) { accA[k] = 0ull; accB[k] = 0ull; }

    const ulonglong2* semb2 = (const ulonglong2*)(sem + b * NN * DD);
    const float* wrow0 = (const float*)wsm4[rbase + 0];
    const float* wrow1 = (const float*)wsm4[rbase + 1];
    const float* wrow2 = (const float*)wsm4[rbase + 2];
    const float* wrow3 = (const float*)wsm4[rbase + 3];

#pragma unroll 4
    for (int j = 0; j < NN; j++) {
        ulonglong2 v = semb2[j * 32 + d4];
        ull w0 = pack2(wrow0[j], wrow0[j]);
        ull w1 = pack2(wrow1[j], wrow1[j]);
        ull w2 = pack2(wrow2[j], wrow2[j]);
        ull w3 = pack2(wrow3[j], wrow3[j]);
        accA[0] = fma2(w0, v.x, accA[0]); accB[0] = fma2(w0, v.y, accB[0]);
        accA[1] = fma2(w1, v.x, accA[1]); accB[1] = fma2(w1, v.y, accB[1]);
        accA[2] = fma2(w2, v.x, accA[2]); accB[2] = fma2(w2, v.y, accB[2]);
        accA[3] = fma2(w3, v.x, accA[3]); accB[3] = fma2(w3, v.y, accB[3]);
    }

#pragma unroll
    for (int k = 0; k < 4; k++) {
        float sc = wscale[rbase + k];
        float4 o;
        unpack2(accA[k], o.x, o.y);
        unpack2(accB[k], o.z, o.w);
        o.x *= sc; o.y *= sc; o.z *= sc; o.w *= sc;
        ((float4*)(out + ((b * NN) + i0 + rbase + k) * DD))[d4] = o;
    }
}

// ---------------------------------------------------------------------------
extern "C" void kernel_launch(void* const* d_in, const int* in_sizes, int n_in,
                              void* d_out, int out_size)
{
    const float* sem  = (const float*)d_in[0];
    const float* strv = (const float*)d_in[1];
    const int*   adj  = (const int*)d_in[2];
    const float* aw   = (const float*)d_in[3];
    const float* swt  = (const float*)d_in[4];
    const float* a1   = (const float*)d_in[5];
    const float* a2   = (const float*)d_in[6];
    float* out = (float*)d_out;

    cudaFuncSetAttribute(scores_kernel,
                         cudaFuncAttributeMaxDynamicSharedMemorySize, SMEM_BYTES);

    scores_kernel<<<dim3(NN / TI, BB), 256, SMEM_BYTES>>>(
        sem, strv, adj, aw, swt);
    combine_kernel<<<dim3(NN / 32, BB), 256>>>(sem, a1, a2, out);
}

// round 12
// speedup vs baseline: 2.1102x; 1.3708x over previous
#include <cuda_runtime.h>
#include <cuda_bf16.h>
#include <cstdint>

#define BB 32
#define NN 256
#define DD 128
#define NEG_MASK (-9000000.0f)
#define LEAK 0.2f

// Scratch for masked relation scores (allowed: __device__ globals)
__device__ float g_s1[BB * NN * NN];
__device__ float g_s2[BB * NN * NN];

typedef unsigned long long ull;

// ---------------------------------------------------------------------------
// f32x2 packed-math helpers (combine kernel)
// ---------------------------------------------------------------------------
__device__ __forceinline__ ull fma2(ull a, ull b, ull c) {
    ull d;
    asm("fma.rn.f32x2 %0, %1, %2, %3;" : "=l"(d) : "l"(a), "l"(b), "l"(c));
    return d;
}
__device__ __forceinline__ ull pack2(float lo, float hi) {
    ull d;
    asm("mov.b64 %0, {%1, %2};" : "=l"(d) : "f"(lo), "f"(hi));
    return d;
}
__device__ __forceinline__ void unpack2(ull v, float& lo, float& hi) {
    asm("mov.b64 {%0, %1}, %2;" : "=f"(lo), "=f"(hi) : "l"(v));
}

// ---------------------------------------------------------------------------
// mma.sync helpers (compute_100 baseline — no tcgen05 in this toolchain)
// ---------------------------------------------------------------------------
__device__ __forceinline__ uint32_t smem_u32(const void* p) {
    uint32_t a;
    asm("{ .reg .u64 t; cvta.to.shared.u64 t, %1; cvt.u32.u64 %0, t; }"
        : "=r"(a) : "l"(p));
    return a;
}

__device__ __forceinline__ void ldsm4(uint32_t* r, uint32_t addr) {
    asm volatile("ldmatrix.sync.aligned.m8n8.x4.shared.b16 {%0,%1,%2,%3}, [%4];"
                 : "=r"(r[0]), "=r"(r[1]), "=r"(r[2]), "=r"(r[3]) : "r"(addr));
}
__device__ __forceinline__ void ldsm2(uint32_t* r, uint32_t addr) {
    asm volatile("ldmatrix.sync.aligned.m8n8.x2.shared.b16 {%0,%1}, [%2];"
                 : "=r"(r[0]), "=r"(r[1]) : "r"(addr));
}
__device__ __forceinline__ void mma16816(float* c, const uint32_t* a,
                                         const uint32_t* b) {
    asm volatile(
        "mma.sync.aligned.m16n8k16.row.col.f32.bf16.bf16.f32 "
        "{%0,%1,%2,%3}, {%4,%5,%6,%7}, {%8,%9}, {%0,%1,%2,%3};"
        : "+f"(c[0]), "+f"(c[1]), "+f"(c[2]), "+f"(c[3])
        : "r"(a[0]), "r"(a[1]), "r"(a[2]), "r"(a[3]), "r"(b[0]), "r"(b[1]));
}

// Split f32 pair into bf16-hi pair + bf16-lo (residual) pair, packed u32 each.
__device__ __forceinline__ void split2(float p0, float p1,
                                       uint32_t& hi, uint32_t& lo) {
    asm("cvt.rn.satfinite.bf16x2.f32 %0, %1, %2;" : "=r"(hi) : "f"(p1), "f"(p0));
    float f0 = __uint_as_float(hi << 16);
    float f1 = __uint_as_float(hi & 0xffff0000u);
    float r0 = p0 - f0, r1 = p1 - f1;
    asm("cvt.rn.satfinite.bf16x2.f32 %0, %1, %2;" : "=r"(lo) : "f"(r1), "f"(r0));
}

// ---------------------------------------------------------------------------
// Kernel A (mma.sync): E_r = (H .* w_r) @ H^T, split-bf16 x3, adj-gated epilogue.
// grid (4 jt, 4 it, 32 b) x 256 threads, 64x64 tile, 8 warps = 4r x 2 i-halves.
// smem union: staging A[4r][2sp][64][40bf16] + B[2sp][64][40]  (51200 B)
//             / epilogue C [4r][64][66] f32                    (67584 B)
// ---------------------------------------------------------------------------
#define SA_OFF 0
#define SB_OFF 40960
#define SMEMB 67584

extern __shared__ unsigned char smraw[];

__global__ __launch_bounds__(256, 2) void scores_mma_kernel(
    const float* __restrict__ sem, const float* __restrict__ strv,
    const int* __restrict__ adj,
    const float* __restrict__ aw, const float* __restrict__ swt)
{
    const int j0 = blockIdx.x * 64, i0 = blockIdx.y * 64, b = blockIdx.z;
    const int tid = threadIdx.x, w = tid >> 5, lane = tid & 31;
    const int rr = w & 3, ihalf = w >> 2;

    const uint32_t smbase = smem_u32(smraw);

    for (int e = 0; e < 2; e++) {
        const float* h = e ? strv : sem;
        const float* wm = e ? swt : aw;
        float* gs = e ? g_s2 : g_s1;

        float c[2][8][4];
#pragma unroll
        for (int mt = 0; mt < 2; mt++)
#pragma unroll
            for (int nt = 0; nt < 8; nt++)
#pragma unroll
                for (int q = 0; q < 4; q++) c[mt][nt][q] = 0.f;

        for (int kc4 = 0; kc4 < 4; kc4++) {
            const int kc = kc4 * 32;
            __syncthreads();   // protect prior readers of the smem union

            // ---- stage A_r tiles: p = h_i[d]*w_r[d], hi/lo bf16 split ----
#pragma unroll
            for (int q = 0; q < 4; q++) {
                int t = tid + 256 * q;
                int m = t >> 4, k2 = t & 15;
                float2 h2 = *(const float2*)&h[((b * NN) + i0 + m) * DD + kc + 2 * k2];
#pragma unroll
                for (int r = 0; r < 4; r++) {
                    float2 wv = *(const float2*)&wm[r * DD + kc + 2 * k2];
                    uint32_t hi, lo;
                    split2(h2.x * wv.x, h2.y * wv.y, hi, lo);
                    *(uint32_t*)(smraw + SA_OFF + ((r * 2 + 0) * 64 + m) * 80 + k2 * 4) = hi;
                    *(uint32_t*)(smraw + SA_OFF + ((r * 2 + 1) * 64 + m) * 80 + k2 * 4) = lo;
                }
            }
            // ---- stage B tile: h_j, hi/lo split ----
#pragma unroll
            for (int q = 0; q < 4; q++) {
                int t = tid + 256 * q;
                int n = t >> 4, k2 = t & 15;
                float2 h2 = *(const float2*)&h[((b * NN) + j0 + n) * DD + kc + 2 * k2];
                uint32_t hi, lo;
                split2(h2.x, h2.y, hi, lo);
                *(uint32_t*)(smraw + SB_OFF + (0 * 64 + n) * 80 + k2 * 4) = hi;
                *(uint32_t*)(smraw + SB_OFF + (1 * 64 + n) * 80 + k2 * 4) = lo;
            }
            __syncthreads();

            // ---- fragments + mma ----
#pragma unroll
            for (int ks = 0; ks < 2; ks++) {
                uint32_t ahi[2][4], alo[2][4];
#pragma unroll
                for (int mt = 0; mt < 2; mt++) {
                    uint32_t ab = smbase + SA_OFF +
                        (uint32_t)(((rr * 2 + 0) * 64 + ihalf * 32 + mt * 16 + (lane & 15)) * 80 +
                                   ks * 32 + (lane >> 4) * 16);
                    ldsm4(ahi[mt], ab);
                    ldsm4(alo[mt], ab + 64 * 80);
                }
#pragma unroll
                for (int nt = 0; nt < 8; nt++) {
                    uint32_t bb = smbase + SB_OFF +
                        (uint32_t)((nt * 8 + (lane & 7)) * 80 + ks * 32 +
                                   ((lane >> 3) & 1) * 16);
                    uint32_t bhi[2], blo[2];
                    ldsm2(bhi, bb);
                    ldsm2(blo, bb + 64 * 80);
#pragma unroll
                    for (int mt = 0; mt < 2; mt++) {
                        mma16816(c[mt][nt], ahi[mt], bhi);
                        mma16816(c[mt][nt], ahi[mt], blo);
                        mma16816(c[mt][nt], alo[mt], bhi);
                    }
                }
            }
        }

        // ---- C -> smem (union reuse; all mma/ldmatrix done) ----
        __syncthreads();
        float* smC = (float*)smraw;
#pragma unroll
        for (int mt = 0; mt < 2; mt++)
#pragma unroll
            for (int nt = 0; nt < 8; nt++) {
                int row0 = ihalf * 32 + mt * 16 + (lane >> 2);
                int col = nt * 8 + (lane & 3) * 2;
                float2* p0 = (float2*)&smC[(rr * 64 + row0) * 66 + col];
                *p0 = make_float2(c[mt][nt][0], c[mt][nt][1]);
                float2* p1 = (float2*)&smC[(rr * 64 + row0 + 8) * 66 + col];
                *p1 = make_float2(c[mt][nt][2], c[mt][nt][3]);
            }
        __syncthreads();

        // ---- gate by adj, leaky, masked store ----
        const int i = tid >> 2, jq = tid & 3;
        const int* arow = &adj[((b * NN) + i0 + i) * NN + j0 + jq * 16];
        float* orow = gs + ((b * NN) + i0 + i) * NN + j0 + jq * 16;
#pragma unroll
        for (int q = 0; q < 4; q++) {
            int4 a4 = ((const int4*)arow)[q];
            int aa[4] = {a4.x, a4.y, a4.z, a4.w};
            float vv[4];
#pragma unroll
            for (int cc = 0; cc < 4; cc++) {
                int a = aa[cc];
                if (a > 0) {
                    float x = smC[((a - 1) * 64 + i) * 66 + jq * 16 + q * 4 + cc];
                    vv[cc] = x >= 0.f ? x : LEAK * x;
                } else {
                    vv[cc] = NEG_MASK;
                }
            }
            ((float4*)orow)[q] = make_float4(vv[0], vv[1], vv[2], vv[3]);
        }
    }
}

// ---------------------------------------------------------------------------
// Kernel B: R3/R10-measured combine (58.5us) — unchanged.
// ---------------------------------------------------------------------------
__device__ __forceinline__ float gsum8(float v) {
#pragma unroll
    for (int o = 1; o < 8; o <<= 1) v += __shfl_xor_sync(0xffffffffu, v, o);
    return v;
}
__device__ __forceinline__ float gmax8(float v) {
#pragma unroll
    for (int o = 1; o < 8; o <<= 1) v = fmaxf(v, __shfl_xor_sync(0xffffffffu, v, o));
    return v;
}

template <int MODE>
__device__ __forceinline__ float pf(float z, float inv) {
    float t = fmaxf(z, 0.f);
    if (MODE == 2) return t * t;
    if (MODE == 1) return t;
    return __powf(t, inv);
}

template <int MODE>
__device__ __forceinline__ float psum32(const float4* X, float tau, float inv) {
    float4 a = make_float4(0.f, 0.f, 0.f, 0.f);
#pragma unroll
    for (int t = 0; t < 8; t++) {
        a.x += pf<MODE>(X[t].x - tau, inv);
        a.y += pf<MODE>(X[t].y - tau, inv);
        a.z += pf<MODE>(X[t].z - tau, inv);
        a.w += pf<MODE>(X[t].w - tau, inv);
    }
    return (a.x + a.y) + (a.z + a.w);
}

template <int M1, int M2>
__device__ __forceinline__ void entmax_pair(
    const float* __restrict__ s1row, const float* __restrict__ s2row,
    float am1_1, float am1_2, float inv1, float inv2,
    float4* __restrict__ wrow4, float* __restrict__ wscale_slot, int s)
{
    float4 X1[8], X2[8];
    float mx1 = -3.4e38f, mx2 = -3.4e38f;
#pragma unroll
    for (int t = 0; t < 8; t++) {
        float4 v = ((const float4*)s1row)[s + 8 * t];
        v.x *= am1_1; v.y *= am1_1; v.z *= am1_1; v.w *= am1_1;
        X1[t] = v;
        mx1 = fmaxf(mx1, fmaxf(fmaxf(v.x, v.y), fmaxf(v.z, v.w)));
        float4 u = ((const float4*)s2row)[s + 8 * t];
        u.x *= am1_2; u.y *= am1_2; u.z *= am1_2; u.w *= am1_2;
        X2[t] = u;
        mx2 = fmaxf(mx2, fmaxf(fmaxf(u.x, u.y), fmaxf(u.z, u.w)));
    }
    mx1 = gmax8(mx1);
    mx2 = gmax8(mx2);

    float tau1 = mx1 - 1.f, tau2 = mx2 - 1.f;
    float dm1 = 1.f - exp2f(-8.f * am1_1);
    float dm2 = 1.f - exp2f(-8.f * am1_2);

    float flo1 = gsum8(psum32<M1>(X1, tau1, inv1)) - 1.f;
    float flo2 = gsum8(psum32<M2>(X2, tau2, inv2)) - 1.f;

#pragma unroll 1
    for (int it = 0; it < 30; it++) {
        dm1 *= 0.5f;
        dm2 *= 0.5f;
        float tm1 = tau1 + dm1;
        float tm2 = tau2 + dm2;
        float ss1 = psum32<M1>(X1, tm1, inv1);
        float ss2 = psum32<M2>(X2, tm2, inv2);
        ss1 = gsum8(ss1);
        ss2 = gsum8(ss2);
        if ((ss1 - 1.f) * flo1 >= 0.f) tau1 = tm1;
        if ((ss2 - 1.f) * flo2 >= 0.f) tau2 = tm2;
    }

    float s1 = 0.f, s2 = 0.f, s3 = 0.f;
#pragma unroll
    for (int t = 0; t < 8; t++) {
        float4 p1, p2, wf;
        p1.x = pf<M1>(X1[t].x - tau1, inv1); p2.x = pf<M2>(X2[t].x - tau2, inv2);
        p1.y = pf<M1>(X1[t].y - tau1, inv1); p2.y = pf<M2>(X2[t].y - tau2, inv2);
        p1.z = pf<M1>(X1[t].z - tau1, inv1); p2.z = pf<M2>(X2[t].z - tau2, inv2);
        p1.w = pf<M1>(X1[t].w - tau1, inv1); p2.w = pf<M2>(X2[t].w - tau2, inv2);
        wf.x = p1.x * p2.x; wf.y = p1.y * p2.y;
        wf.z = p1.z * p2.z; wf.w = p1.w * p2.w;
        s1 += (p1.x + p1.y) + (p1.z + p1.w);
        s2 += (p2.x + p2.y) + (p2.z + p2.w);
        s3 += (wf.x + wf.y) + (wf.z + wf.w);
        wrow4[s + 8 * t] = wf;
    }
    s1 = gsum8(s1);
    s2 = gsum8(s2);
    s3 = gsum8(s3);
    float scale = 1.f / (s3 + 1e-7f * s1 * s2);
    if (s == 0) *wscale_slot = scale;
}

__global__ __launch_bounds__(256, 2) void combine_kernel(
    const float* __restrict__ sem,
    const float* __restrict__ alpha1p, const float* __restrict__ alpha2p,
    float* __restrict__ out)
{
    __shared__ float4 wsm4[32][NN / 4];
    __shared__ float wscale[32];

    const int b = blockIdx.y;
    const int i0 = blockIdx.x * 32;
    const int tid = threadIdx.x;
    const int w = tid >> 5, lane = tid & 31;
    const int g = lane >> 3, s = lane & 7;
    const int rowLocal = w * 4 + g;
    const int row = i0 + rowLocal;

    const float* s1row = g_s1 + ((b * NN) + row) * NN;
    const float* s2row = g_s2 + ((b * NN) + row) * NN;

    float a1 = alpha1p[0], a2 = alpha2p[0];
    float am1_1 = a1 - 1.f, am1_2 = a2 - 1.f;
    float inv1 = 1.f / am1_1, inv2 = 1.f / am1_2;

    int m1 = (fabsf(a1 - 1.5f) < 1e-4f) ? 2 : ((fabsf(a1 - 2.f) < 1e-4f) ? 1 : 0);
    int m2 = (fabsf(a2 - 1.5f) < 1e-4f) ? 2 : ((fabsf(a2 - 2.f) < 1e-4f) ? 1 : 0);

    if (m1 == 2 && m2 == 1)
        entmax_pair<2, 1>(s1row, s2row, am1_1, am1_2, inv1, inv2,
                          wsm4[rowLocal], &wscale[rowLocal], s);
    else if (m1 == 1 && m2 == 2)
        entmax_pair<1, 2>(s1row, s2row, am1_1, am1_2, inv1, inv2,
                          wsm4[rowLocal], &wscale[rowLocal], s);
    else
        entmax_pair<0, 0>(s1row, s2row, am1_1, am1_2, inv1, inv2,
                          wsm4[rowLocal], &wscale[rowLocal], s);

    __syncthreads();

    const int d4 = tid & 31, rbase = (tid >> 5) * 4;
    ull accA[4], accB[4];
#pragma unroll
    for (int k = 0; k < 4; k++) { accA[k] = 0ull; accB[k] = 0ull; }

    const ulonglong2* semb2 = (const ulonglong2*)(sem + b * NN * DD);
    const float* wrow0 = (const float*)wsm4[rbase + 0];
    const float* wrow1 = (const float*)wsm4[rbase + 1];
    const float* wrow2 = (const float*)wsm4[rbase + 2];
    const float* wrow3 = (const float*)wsm4[rbase + 3];

#pragma unroll 4
    for (int j = 0; j < NN; j++) {
        ulonglong2 vv = semb2[j * 32 + d4];
        ull w0 = pack2(wrow0[j], wrow0[j]);
        ull w1 = pack2(wrow1[j], wrow1[j]);
        ull w2 = pack2(wrow2[j], wrow2[j]);
        ull w3 = pack2(wrow3[j], wrow3[j]);
        accA[0] = fma2(w0, vv.x, accA[0]); accB[0] = fma2(w0, vv.y, accB[0]);
        accA[1] = fma2(w1, vv.x, accA[1]); accB[1] = fma2(w1, vv.y, accB[1]);
        accA[2] = fma2(w2, vv.x, accA[2]); accB[2] = fma2(w2, vv.y, accB[2]);
        accA[3] = fma2(w3, vv.x, accA[3]); accB[3] = fma2(w3, vv.y, accB[3]);
    }

#pragma unroll
    for (int k = 0; k < 4; k++) {
        float sc = wscale[rbase + k];
        float4 o;
        unpack2(accA[k], o.x, o.y);
        unpack2(accB[k], o.z, o.w);
        o.x *= sc; o.y *= sc; o.z *= sc; o.w *= sc;
        ((float4*)(out + ((b * NN) + i0 + rbase + k) * DD))[d4] = o;
    }
}

// ---------------------------------------------------------------------------
extern "C" void kernel_launch(void* const* d_in, const int* in_sizes, int n_in,
                              void* d_out, int out_size)
{
    const float* sem  = (const float*)d_in[0];
    const float* strv = (const float*)d_in[1];
    const int*   adj  = (const int*)d_in[2];
    const float* aw   = (const float*)d_in[3];
    const float* swt  = (const float*)d_in[4];
    const float* a1   = (const float*)d_in[5];
    const float* a2   = (const float*)d_in[6];
    float* out = (float*)d_out;

    cudaFuncSetAttribute(scores_mma_kernel,
                         cudaFuncAttributeMaxDynamicSharedMemorySize, SMEMB);

    scores_mma_kernel<<<dim3(4, 4, BB), 256, SMEMB>>>(sem, strv, adj, aw, swt);
    combine_kernel<<<dim3(NN / 32, BB), 256>>>(sem, a1, a2, out);
}

// round 13
// speedup vs baseline: 2.2565x; 1.0693x over previous
#include <cuda_runtime.h>
#include <cuda_bf16.h>
#include <cstdint>

#define BB 32
#define NN 256
#define DD 128
#define NEG_MASK (-9000000.0f)
#define LEAK 0.2f

// Scratch for masked relation scores (allowed: __device__ globals)
__device__ float g_s1[BB * NN * NN];
__device__ float g_s2[BB * NN * NN];

typedef unsigned long long ull;

// ---------------------------------------------------------------------------
// f32x2 packed-math helpers (combine kernel)
// ---------------------------------------------------------------------------
__device__ __forceinline__ ull fma2(ull a, ull b, ull c) {
    ull d;
    asm("fma.rn.f32x2 %0, %1, %2, %3;" : "=l"(d) : "l"(a), "l"(b), "l"(c));
    return d;
}
__device__ __forceinline__ ull pack2(float lo, float hi) {
    ull d;
    asm("mov.b64 %0, {%1, %2};" : "=l"(d) : "f"(lo), "f"(hi));
    return d;
}
__device__ __forceinline__ void unpack2(ull v, float& lo, float& hi) {
    asm("mov.b64 {%0, %1}, %2;" : "=f"(lo), "=f"(hi) : "l"(v));
}

// ---------------------------------------------------------------------------
// mma.sync helpers (compute_100 baseline — no tcgen05 in this toolchain)
// ---------------------------------------------------------------------------
__device__ __forceinline__ uint32_t smem_u32(const void* p) {
    uint32_t a;
    asm("{ .reg .u64 t; cvta.to.shared.u64 t, %1; cvt.u32.u64 %0, t; }"
        : "=r"(a) : "l"(p));
    return a;
}

__device__ __forceinline__ void ldsm4(uint32_t* r, uint32_t addr) {
    asm volatile("ldmatrix.sync.aligned.m8n8.x4.shared.b16 {%0,%1,%2,%3}, [%4];"
                 : "=r"(r[0]), "=r"(r[1]), "=r"(r[2]), "=r"(r[3]) : "r"(addr));
}
__device__ __forceinline__ void ldsm2(uint32_t* r, uint32_t addr) {
    asm volatile("ldmatrix.sync.aligned.m8n8.x2.shared.b16 {%0,%1}, [%2];"
                 : "=r"(r[0]), "=r"(r[1]) : "r"(addr));
}
__device__ __forceinline__ void mma16816(float* c, const uint32_t* a,
                                         const uint32_t* b) {
    asm volatile(
        "mma.sync.aligned.m16n8k16.row.col.f32.bf16.bf16.f32 "
        "{%0,%1,%2,%3}, {%4,%5,%6,%7}, {%8,%9}, {%0,%1,%2,%3};"
        : "+f"(c[0]), "+f"(c[1]), "+f"(c[2]), "+f"(c[3])
        : "r"(a[0]), "r"(a[1]), "r"(a[2]), "r"(a[3]), "r"(b[0]), "r"(b[1]));
}

// Split f32 pair into bf16-hi pair + bf16-lo (residual) pair, packed u32 each.
__device__ __forceinline__ void split2(float p0, float p1,
                                       uint32_t& hi, uint32_t& lo) {
    asm("cvt.rn.satfinite.bf16x2.f32 %0, %1, %2;" : "=r"(hi) : "f"(p1), "f"(p0));
    float f0 = __uint_as_float(hi << 16);
    float f1 = __uint_as_float(hi & 0xffff0000u);
    float r0 = p0 - f0, r1 = p1 - f1;
    asm("cvt.rn.satfinite.bf16x2.f32 %0, %1, %2;" : "=r"(lo) : "f"(r1), "f"(r0));
}

// ---------------------------------------------------------------------------
// Kernel A (mma.sync): E_r = (H .* w_r) @ H^T, split-bf16 x3, adj-gated epilogue.
// grid (4 jt, 4 it, 32 b) x 256 threads, 64x64 tile, 8 warps = 4r x 2 i-halves.
// (unchanged — measured 46.1us, R12-verified)
// ---------------------------------------------------------------------------
#define SA_OFF 0
#define SB_OFF 40960
#define SMEMB 67584

extern __shared__ unsigned char smraw[];

__global__ __launch_bounds__(256, 2) void scores_mma_kernel(
    const float* __restrict__ sem, const float* __restrict__ strv,
    const int* __restrict__ adj,
    const float* __restrict__ aw, const float* __restrict__ swt)
{
    const int j0 = blockIdx.x * 64, i0 = blockIdx.y * 64, b = blockIdx.z;
    const int tid = threadIdx.x, w = tid >> 5, lane = tid & 31;
    const int rr = w & 3, ihalf = w >> 2;

    const uint32_t smbase = smem_u32(smraw);

    for (int e = 0; e < 2; e++) {
        const float* h = e ? strv : sem;
        const float* wm = e ? swt : aw;
        float* gs = e ? g_s2 : g_s1;

        float c[2][8][4];
#pragma unroll
        for (int mt = 0; mt < 2; mt++)
#pragma unroll
            for (int nt = 0; nt < 8; nt++)
#pragma unroll
                for (int q = 0; q < 4; q++) c[mt][nt][q] = 0.f;

        for (int kc4 = 0; kc4 < 4; kc4++) {
            const int kc = kc4 * 32;
            __syncthreads();   // protect prior readers of the smem union

            // ---- stage A_r tiles: p = h_i[d]*w_r[d], hi/lo bf16 split ----
#pragma unroll
            for (int q = 0; q < 4; q++) {
                int t = tid + 256 * q;
                int m = t >> 4, k2 = t & 15;
                float2 h2 = *(const float2*)&h[((b * NN) + i0 + m) * DD + kc + 2 * k2];
#pragma unroll
                for (int r = 0; r < 4; r++) {
                    float2 wv = *(const float2*)&wm[r * DD + kc + 2 * k2];
                    uint32_t hi, lo;
                    split2(h2.x * wv.x, h2.y * wv.y, hi, lo);
                    *(uint32_t*)(smraw + SA_OFF + ((r * 2 + 0) * 64 + m) * 80 + k2 * 4) = hi;
                    *(uint32_t*)(smraw + SA_OFF + ((r * 2 + 1) * 64 + m) * 80 + k2 * 4) = lo;
                }
            }
            // ---- stage B tile: h_j, hi/lo split ----
#pragma unroll
            for (int q = 0; q < 4; q++) {
                int t = tid + 256 * q;
                int n = t >> 4, k2 = t & 15;
                float2 h2 = *(const float2*)&h[((b * NN) + j0 + n) * DD + kc + 2 * k2];
                uint32_t hi, lo;
                split2(h2.x, h2.y, hi, lo);
                *(uint32_t*)(smraw + SB_OFF + (0 * 64 + n) * 80 + k2 * 4) = hi;
                *(uint32_t*)(smraw + SB_OFF + (1 * 64 + n) * 80 + k2 * 4) = lo;
            }
            __syncthreads();

            // ---- fragments + mma ----
#pragma unroll
            for (int ks = 0; ks < 2; ks++) {
                uint32_t ahi[2][4], alo[2][4];
#pragma unroll
                for (int mt = 0; mt < 2; mt++) {
                    uint32_t ab = smbase + SA_OFF +
                        (uint32_t)(((rr * 2 + 0) * 64 + ihalf * 32 + mt * 16 + (lane & 15)) * 80 +
                                   ks * 32 + (lane >> 4) * 16);
                    ldsm4(ahi[mt], ab);
                    ldsm4(alo[mt], ab + 64 * 80);
                }
#pragma unroll
                for (int nt = 0; nt < 8; nt++) {
                    uint32_t bb = smbase + SB_OFF +
                        (uint32_t)((nt * 8 + (lane & 7)) * 80 + ks * 32 +
                                   ((lane >> 3) & 1) * 16);
                    uint32_t bhi[2], blo[2];
                    ldsm2(bhi, bb);
                    ldsm2(blo, bb + 64 * 80);
#pragma unroll
                    for (int mt = 0; mt < 2; mt++) {
                        mma16816(c[mt][nt], ahi[mt], bhi);
                        mma16816(c[mt][nt], ahi[mt], blo);
                        mma16816(c[mt][nt], alo[mt], bhi);
                    }
                }
            }
        }

        // ---- C -> smem (union reuse; all mma/ldmatrix done) ----
        __syncthreads();
        float* smC = (float*)smraw;
#pragma unroll
        for (int mt = 0; mt < 2; mt++)
#pragma unroll
            for (int nt = 0; nt < 8; nt++) {
                int row0 = ihalf * 32 + mt * 16 + (lane >> 2);
                int col = nt * 8 + (lane & 3) * 2;
                float2* p0 = (float2*)&smC[(rr * 64 + row0) * 66 + col];
                *p0 = make_float2(c[mt][nt][0], c[mt][nt][1]);
                float2* p1 = (float2*)&smC[(rr * 64 + row0 + 8) * 66 + col];
                *p1 = make_float2(c[mt][nt][2], c[mt][nt][3]);
            }
        __syncthreads();

        // ---- gate by adj, leaky, masked store ----
        const int i = tid >> 2, jq = tid & 3;
        const int* arow = &adj[((b * NN) + i0 + i) * NN + j0 + jq * 16];
        float* orow = gs + ((b * NN) + i0 + i) * NN + j0 + jq * 16;
#pragma unroll
        for (int q = 0; q < 4; q++) {
            int4 a4 = ((const int4*)arow)[q];
            int aa[4] = {a4.x, a4.y, a4.z, a4.w};
            float vv[4];
#pragma unroll
            for (int cc = 0; cc < 4; cc++) {
                int a = aa[cc];
                if (a > 0) {
                    float x = smC[((a - 1) * 64 + i) * 66 + jq * 16 + q * 4 + cc];
                    vv[cc] = x >= 0.f ? x : LEAK * x;
                } else {
                    vv[cc] = NEG_MASK;
                }
            }
            ((float4*)orow)[q] = make_float4(vv[0], vv[1], vv[2], vv[3]);
        }
    }
}

// ---------------------------------------------------------------------------
// Kernel B: combine. Change vs R12: specialized entmax paths run 20 bisect
// iterations (tau err <= 2^-20 ~ 1e-6, invisible at 1e-3 threshold; reference's
// own iters 25-30 are fp32 no-ops). Generic path keeps 30.
// ---------------------------------------------------------------------------
__device__ __forceinline__ float gsum8(float v) {
#pragma unroll
    for (int o = 1; o < 8; o <<= 1) v += __shfl_xor_sync(0xffffffffu, v, o);
    return v;
}
__device__ __forceinline__ float gmax8(float v) {
#pragma unroll
    for (int o = 1; o < 8; o <<= 1) v = fmaxf(v, __shfl_xor_sync(0xffffffffu, v, o));
    return v;
}

template <int MODE>
__device__ __forceinline__ float pf(float z, float inv) {
    float t = fmaxf(z, 0.f);
    if (MODE == 2) return t * t;
    if (MODE == 1) return t;
    return __powf(t, inv);
}

template <int MODE>
__device__ __forceinline__ float psum32(const float4* X, float tau, float inv) {
    float4 a = make_float4(0.f, 0.f, 0.f, 0.f);
#pragma unroll
    for (int t = 0; t < 8; t++) {
        a.x += pf<MODE>(X[t].x - tau, inv);
        a.y += pf<MODE>(X[t].y - tau, inv);
        a.z += pf<MODE>(X[t].z - tau, inv);
        a.w += pf<MODE>(X[t].w - tau, inv);
    }
    return (a.x + a.y) + (a.z + a.w);
}

template <int M1, int M2>
__device__ __forceinline__ void entmax_pair(
    const float* __restrict__ s1row, const float* __restrict__ s2row,
    float am1_1, float am1_2, float inv1, float inv2,
    float4* __restrict__ wrow4, float* __restrict__ wscale_slot, int s)
{
    float4 X1[8], X2[8];
    float mx1 = -3.4e38f, mx2 = -3.4e38f;
#pragma unroll
    for (int t = 0; t < 8; t++) {
        float4 v = ((const float4*)s1row)[s + 8 * t];
        v.x *= am1_1; v.y *= am1_1; v.z *= am1_1; v.w *= am1_1;
        X1[t] = v;
        mx1 = fmaxf(mx1, fmaxf(fmaxf(v.x, v.y), fmaxf(v.z, v.w)));
        float4 u = ((const float4*)s2row)[s + 8 * t];
        u.x *= am1_2; u.y *= am1_2; u.z *= am1_2; u.w *= am1_2;
        X2[t] = u;
        mx2 = fmaxf(mx2, fmaxf(fmaxf(u.x, u.y), fmaxf(u.z, u.w)));
    }
    mx1 = gmax8(mx1);
    mx2 = gmax8(mx2);

    float tau1 = mx1 - 1.f, tau2 = mx2 - 1.f;
    float dm1 = 1.f - exp2f(-8.f * am1_1);
    float dm2 = 1.f - exp2f(-8.f * am1_2);

    float flo1 = gsum8(psum32<M1>(X1, tau1, inv1)) - 1.f;
    float flo2 = gsum8(psum32<M2>(X2, tau2, inv2)) - 1.f;

    const int NBIS = (M1 == 0 || M2 == 0) ? 30 : 20;

#pragma unroll 1
    for (int it = 0; it < NBIS; it++) {
        dm1 *= 0.5f;
        dm2 *= 0.5f;
        float tm1 = tau1 + dm1;
        float tm2 = tau2 + dm2;
        float ss1 = psum32<M1>(X1, tm1, inv1);
        float ss2 = psum32<M2>(X2, tm2, inv2);
        ss1 = gsum8(ss1);
        ss2 = gsum8(ss2);
        if ((ss1 - 1.f) * flo1 >= 0.f) tau1 = tm1;
        if ((ss2 - 1.f) * flo2 >= 0.f) tau2 = tm2;
    }

    float s1 = 0.f, s2 = 0.f, s3 = 0.f;
#pragma unroll
    for (int t = 0; t < 8; t++) {
        float4 p1, p2, wf;
        p1.x = pf<M1>(X1[t].x - tau1, inv1); p2.x = pf<M2>(X2[t].x - tau2, inv2);
        p1.y = pf<M1>(X1[t].y - tau1, inv1); p2.y = pf<M2>(X2[t].y - tau2, inv2);
        p1.z = pf<M1>(X1[t].z - tau1, inv1); p2.z = pf<M2>(X2[t].z - tau2, inv2);
        p1.w = pf<M1>(X1[t].w - tau1, inv1); p2.w = pf<M2>(X2[t].w - tau2, inv2);
        wf.x = p1.x * p2.x; wf.y = p1.y * p2.y;
        wf.z = p1.z * p2.z; wf.w = p1.w * p2.w;
        s1 += (p1.x + p1.y) + (p1.z + p1.w);
        s2 += (p2.x + p2.y) + (p2.z + p2.w);
        s3 += (wf.x + wf.y) + (wf.z + wf.w);
        wrow4[s + 8 * t] = wf;
    }
    s1 = gsum8(s1);
    s2 = gsum8(s2);
    s3 = gsum8(s3);
    float scale = 1.f / (s3 + 1e-7f * s1 * s2);
    if (s == 0) *wscale_slot = scale;
}

__global__ __launch_bounds__(256, 2) void combine_kernel(
    const float* __restrict__ sem,
    const float* __restrict__ alpha1p, const float* __restrict__ alpha2p,
    float* __restrict__ out)
{
    __shared__ float4 wsm4[32][NN / 4];
    __shared__ float wscale[32];

    const int b = blockIdx.y;
    const int i0 = blockIdx.x * 32;
    const int tid = threadIdx.x;
    const int w = tid >> 5, lane = tid & 31;
    const int g = lane >> 3, s = lane & 7;
    const int rowLocal = w * 4 + g;
    const int row = i0 + rowLocal;

    const float* s1row = g_s1 + ((b * NN) + row) * NN;
    const float* s2row = g_s2 + ((b * NN) + row) * NN;

    float a1 = alpha1p[0], a2 = alpha2p[0];
    float am1_1 = a1 - 1.f, am1_2 = a2 - 1.f;
    float inv1 = 1.f / am1_1, inv2 = 1.f / am1_2;

    int m1 = (fabsf(a1 - 1.5f) < 1e-4f) ? 2 : ((fabsf(a1 - 2.f) < 1e-4f) ? 1 : 0);
    int m2 = (fabsf(a2 - 1.5f) < 1e-4f) ? 2 : ((fabsf(a2 - 2.f) < 1e-4f) ? 1 : 0);

    if (m1 == 2 && m2 == 1)
        entmax_pair<2, 1>(s1row, s2row, am1_1, am1_2, inv1, inv2,
                          wsm4[rowLocal], &wscale[rowLocal], s);
    else if (m1 == 1 && m2 == 2)
        entmax_pair<1, 2>(s1row, s2row, am1_1, am1_2, inv1, inv2,
                          wsm4[rowLocal], &wscale[rowLocal], s);
    else if (m1 == 2 && m2 == 2)
        entmax_pair<2, 2>(s1row, s2row, am1_1, am1_2, inv1, inv2,
                          wsm4[rowLocal], &wscale[rowLocal], s);
    else if (m1 == 1 && m2 == 1)
        entmax_pair<1, 1>(s1row, s2row, am1_1, am1_2, inv1, inv2,
                          wsm4[rowLocal], &wscale[rowLocal], s);
    else
        entmax_pair<0, 0>(s1row, s2row, am1_1, am1_2, inv1, inv2,
                          wsm4[rowLocal], &wscale[rowLocal], s);

    __syncthreads();

    const int d4 = tid & 31, rbase = (tid >> 5) * 4;
    ull accA[4], accB[4];
#pragma unroll
    for (int k = 0; k < 4; k++) { accA[k] = 0ull; accB[k] = 0ull; }

    const ulonglong2* semb2 = (const ulonglong2*)(sem + b * NN * DD);
    const float* wrow0 = (const float*)wsm4[rbase + 0];
    const float* wrow1 = (const float*)wsm4[rbase + 1];
    const float* wrow2 = (const float*)wsm4[rbase + 2];
    const float* wrow3 = (const float*)wsm4[rbase + 3];

#pragma unroll 4
    for (int j = 0; j < NN; j++) {
        ulonglong2 vv = semb2[j * 32 + d4];
        ull w0 = pack2(wrow0[j], wrow0[j]);
        ull w1 = pack2(wrow1[j], wrow1[j]);
        ull w2 = pack2(wrow2[j], wrow2[j]);
        ull w3 = pack2(wrow3[j], wrow3[j]);
        accA[0] = fma2(w0, vv.x, accA[0]); accB[0] = fma2(w0, vv.y, accB[0]);
        accA[1] = fma2(w1, vv.x, accA[1]); accB[1] = fma2(w1, vv.y, accB[1]);
        accA[2] = fma2(w2, vv.x, accA[2]); accB[2] = fma2(w2, vv.y, accB[2]);
        accA[3] = fma2(w3, vv.x, accA[3]); accB[3] = fma2(w3, vv.y, accB[3]);
    }

#pragma unroll
    for (int k = 0; k < 4; k++) {
        float sc = wscale[rbase + k];
        float4 o;
        unpack2(accA[k], o.x, o.y);
        unpack2(accB[k], o.z, o.w);
        o.x *= sc; o.y *= sc; o.z *= sc; o.w *= sc;
        ((float4*)(out + ((b * NN) + i0 + rbase + k) * DD))[d4] = o;
    }
}

// ---------------------------------------------------------------------------
extern "C" void kernel_launch(void* const* d_in, const int* in_sizes, int n_in,
                              void* d_out, int out_size)
{
    const float* sem  = (const float*)d_in[0];
    const float* strv = (const float*)d_in[1];
    const int*   adj  = (const int*)d_in[2];
    const float* aw   = (const float*)d_in[3];
    const float* swt  = (const float*)d_in[4];
    const float* a1   = (const float*)d_in[5];
    const float* a2   = (const float*)d_in[6];
    float* out = (float*)d_out;

    cudaFuncSetAttribute(scores_mma_kernel,
                         cudaFuncAttributeMaxDynamicSharedMemorySize, SMEMB);

    scores_mma_kernel<<<dim3(4, 4, BB), 256, SMEMB>>>(sem, strv, adj, aw, swt);
    combine_kernel<<<dim3(NN / 32, BB), 256>>>(sem, a1, a2, out);
}

// round 15
// speedup vs baseline: 2.4340x; 1.0787x over previous
#include <cuda_runtime.h>
#include <cuda_bf16.h>
#include <cstdint>

#define BB 32
#define NN 256
#define DD 128
#define NEG_MASK (-9000000.0f)
#define LEAK 0.2f

// Scratch for masked relation scores (allowed: __device__ globals)
__device__ float g_s1[BB * NN * NN];
__device__ float g_s2[BB * NN * NN];

typedef unsigned long long ull;

// ---------------------------------------------------------------------------
// f32x2 packed-math helpers (combine kernel)
// ---------------------------------------------------------------------------
__device__ __forceinline__ ull fma2(ull a, ull b, ull c) {
    ull d;
    asm("fma.rn.f32x2 %0, %1, %2, %3;" : "=l"(d) : "l"(a), "l"(b), "l"(c));
    return d;
}
__device__ __forceinline__ ull pack2(float lo, float hi) {
    ull d;
    asm("mov.b64 %0, {%1, %2};" : "=l"(d) : "f"(lo), "f"(hi));
    return d;
}
__device__ __forceinline__ void unpack2(ull v, float& lo, float& hi) {
    asm("mov.b64 {%0, %1}, %2;" : "=f"(lo), "=f"(hi) : "l"(v));
}

// ---------------------------------------------------------------------------
// mma.sync helpers (compute_100 baseline — no tcgen05 in this toolchain)
// ---------------------------------------------------------------------------
__device__ __forceinline__ uint32_t smem_u32(const void* p) {
    uint32_t a;
    asm("{ .reg .u64 t; cvta.to.shared.u64 t, %1; cvt.u32.u64 %0, t; }"
        : "=r"(a) : "l"(p));
    return a;
}

__device__ __forceinline__ void ldsm4(uint32_t* r, uint32_t addr) {
    asm volatile("ldmatrix.sync.aligned.m8n8.x4.shared.b16 {%0,%1,%2,%3}, [%4];"
                 : "=r"(r[0]), "=r"(r[1]), "=r"(r[2]), "=r"(r[3]) : "r"(addr));
}
__device__ __forceinline__ void ldsm2(uint32_t* r, uint32_t addr) {
    asm volatile("ldmatrix.sync.aligned.m8n8.x2.shared.b16 {%0,%1}, [%2];"
                 : "=r"(r[0]), "=r"(r[1]) : "r"(addr));
}
__device__ __forceinline__ void mma16816(float* c, const uint32_t* a,
                                         const uint32_t* b) {
    asm volatile(
        "mma.sync.aligned.m16n8k16.row.col.f32.bf16.bf16.f32 "
        "{%0,%1,%2,%3}, {%4,%5,%6,%7}, {%8,%9}, {%0,%1,%2,%3};"
        : "+f"(c[0]), "+f"(c[1]), "+f"(c[2]), "+f"(c[3])
        : "r"(a[0]), "r"(a[1]), "r"(a[2]), "r"(a[3]), "r"(b[0]), "r"(b[1]));
}

// Split f32 pair into bf16-hi pair + bf16-lo (residual) pair, packed u32 each.
__device__ __forceinline__ void split2(float p0, float p1,
                                       uint32_t& hi, uint32_t& lo) {
    asm("cvt.rn.satfinite.bf16x2.f32 %0, %1, %2;" : "=r"(hi) : "f"(p1), "f"(p0));
    float f0 = __uint_as_float(hi << 16);
    float f1 = __uint_as_float(hi & 0xffff0000u);
    float r0 = p0 - f0, r1 = p1 - f1;
    asm("cvt.rn.satfinite.bf16x2.f32 %0, %1, %2;" : "=r"(lo) : "f"(r1), "f"(r0));
}

// ---------------------------------------------------------------------------
// Kernel A (mma.sync, row-panel): E_r = (H .* w_r) @ H^T, split-bf16 x3.
// grid (8 i-panels, 32 b) x 256 threads. CTA = 32 i-rows x all 256 j.
// A panel [4r][2sp][32m][K=128] staged ONCE (68KB); per j-tile B [2sp][64n][K]
// (34KB, reused as C buffer). Warp = (r, n-half): 32m x 32n accumulators.
// pitch 272B -> ldsm conflict-free (68 words = 4 mod 32).
// ---------------------------------------------------------------------------
#define PIT 272
#define SA_OFF 0
#define SB_OFF (4 * 2 * 32 * PIT)          // 69632
#define SMEMB (SB_OFF + 2 * 64 * PIT)      // 104448

extern __shared__ unsigned char smraw[];

__global__ __launch_bounds__(256, 2) void scores_mma_kernel(
    const float* __restrict__ sem, const float* __restrict__ strv,
    const int* __restrict__ adj,
    const float* __restrict__ aw, const float* __restrict__ swt)
{
    const int i0 = blockIdx.x * 32, b = blockIdx.y;
    const int tid = threadIdx.x, w = tid >> 5, lane = tid & 31;
    const int rr = w & 3, nh = w >> 2;

    const uint32_t smbase = smem_u32(smraw);

    for (int e = 0; e < 2; e++) {
        const float* h = e ? strv : sem;
        const float* wm = e ? swt : aw;
        float* gs = e ? g_s2 : g_s1;

        __syncthreads();   // prior readers of A region done

        // ---- stage A panel once: p = h_i[d]*w_r[d], hi/lo split, full K ----
        {
            const int k2 = tid & 63;          // k-pair index (fixed per thread)
            const int mb = tid >> 6;          // row group
            float2 wreg[4];
#pragma unroll
            for (int r = 0; r < 4; r++)
                wreg[r] = *(const float2*)&wm[r * DD + 2 * k2];
#pragma unroll
            for (int q = 0; q < 8; q++) {
                int m = mb * 8 + q;
                float2 h2 = *(const float2*)&h[((b * NN) + i0 + m) * DD + 2 * k2];
#pragma unroll
                for (int r = 0; r < 4; r++) {
                    uint32_t hi, lo;
                    split2(h2.x * wreg[r].x, h2.y * wreg[r].y, hi, lo);
                    *(uint32_t*)(smraw + SA_OFF + ((r * 2 + 0) * 32 + m) * PIT + k2 * 4) = hi;
                    *(uint32_t*)(smraw + SA_OFF + ((r * 2 + 1) * 32 + m) * PIT + k2 * 4) = lo;
                }
            }
        }

        for (int jt = 0; jt < 4; jt++) {
            const int j0 = jt * 64;
            __syncthreads();   // A staged (first jt) / prior C readers done

            // ---- stage B tile: h_j hi/lo split, full K ----
#pragma unroll
            for (int q = 0; q < 16; q++) {
                int t = tid + 256 * q;
                int n = t >> 6, k2b = t & 63;
                float2 h2 = *(const float2*)&h[((b * NN) + j0 + n) * DD + 2 * k2b];
                uint32_t hi, lo;
                split2(h2.x, h2.y, hi, lo);
                *(uint32_t*)(smraw + SB_OFF + (0 * 64 + n) * PIT + k2b * 4) = hi;
                *(uint32_t*)(smraw + SB_OFF + (1 * 64 + n) * PIT + k2b * 4) = lo;
            }
            __syncthreads();

            // ---- mma mainloop: warp = (rr, nh), 32m x 32n ----
            float c[2][4][4];
#pragma unroll
            for (int mt = 0; mt < 2; mt++)
#pragma unroll
                for (int nt = 0; nt < 4; nt++)
#pragma unroll
                    for (int q = 0; q < 4; q++) c[mt][nt][q] = 0.f;

#pragma unroll 1
            for (int ks = 0; ks < 8; ks++) {
                uint32_t ahi[2][4], alo[2][4];
#pragma unroll
                for (int mt = 0; mt < 2; mt++) {
                    uint32_t ab = smbase + SA_OFF +
                        (uint32_t)(((rr * 2 + 0) * 32 + mt * 16 + (lane & 15)) * PIT +
                                   ks * 32 + (lane >> 4) * 16);
                    ldsm4(ahi[mt], ab);
                    ldsm4(alo[mt], ab + 32 * PIT);
                }
#pragma unroll
                for (int nt = 0; nt < 4; nt++) {
                    uint32_t bb = smbase + SB_OFF +
                        (uint32_t)((nh * 32 + nt * 8 + (lane & 7)) * PIT +
                                   ks * 32 + ((lane >> 3) & 1) * 16);
                    uint32_t bhi[2], blo[2];
                    ldsm2(bhi, bb);
                    ldsm2(blo, bb + 64 * PIT);
#pragma unroll
                    for (int mt = 0; mt < 2; mt++) {
                        mma16816(c[mt][nt], ahi[mt], bhi);
                        mma16816(c[mt][nt], ahi[mt], blo);
                        mma16816(c[mt][nt], alo[mt], bhi);
                    }
                }
            }

            // ---- C -> smem (reuse B region; all mma done) ----
            __syncthreads();
            float* smC = (float*)(smraw + SB_OFF);
#pragma unroll
            for (int mt = 0; mt < 2; mt++)
#pragma unroll
                for (int nt = 0; nt < 4; nt++) {
                    int row0 = mt * 16 + (lane >> 2);
                    int col = nh * 32 + nt * 8 + (lane & 3) * 2;
                    *(float2*)&smC[(rr * 32 + row0) * 66 + col] =
                        make_float2(c[mt][nt][0], c[mt][nt][1]);
                    *(float2*)&smC[(rr * 32 + row0 + 8) * 66 + col] =
                        make_float2(c[mt][nt][2], c[mt][nt][3]);
                }
            __syncthreads();

            // ---- gate by adj, leaky, masked store ----
            const int i = tid >> 3, jg = tid & 7;
            const int* arow = &adj[((b * NN) + i0 + i) * NN + j0 + jg * 8];
            float* orow = gs + ((b * NN) + i0 + i) * NN + j0 + jg * 8;
#pragma unroll
            for (int q = 0; q < 2; q++) {
                int4 a4 = ((const int4*)arow)[q];
                int aa[4] = {a4.x, a4.y, a4.z, a4.w};
                float vv[4];
#pragma unroll
                for (int cc = 0; cc < 4; cc++) {
                    int a = aa[cc];
                    if (a > 0) {
                        float x = smC[((a - 1) * 32 + i) * 66 + jg * 8 + q * 4 + cc];
                        vv[cc] = x >= 0.f ? x : LEAK * x;
                    } else {
                        vv[cc] = NEG_MASK;
                    }
                }
                ((float4*)orow)[q] = make_float4(vv[0], vv[1], vv[2], vv[3]);
            }
        }
    }
}

// ---------------------------------------------------------------------------
// Kernel B: combine (R13-measured 53.0us) — unchanged.
// ---------------------------------------------------------------------------
__device__ __forceinline__ float gsum8(float v) {
#pragma unroll
    for (int o = 1; o < 8; o <<= 1) v += __shfl_xor_sync(0xffffffffu, v, o);
    return v;
}
__device__ __forceinline__ float gmax8(float v) {
#pragma unroll
    for (int o = 1; o < 8; o <<= 1) v = fmaxf(v, __shfl_xor_sync(0xffffffffu, v, o));
    return v;
}

template <int MODE>
__device__ __forceinline__ float pf(float z, float inv) {
    float t = fmaxf(z, 0.f);
    if (MODE == 2) return t * t;
    if (MODE == 1) return t;
    return __powf(t, inv);
}

template <int MODE>
__device__ __forceinline__ float psum32(const float4* X, float tau, float inv) {
    float4 a = make_float4(0.f, 0.f, 0.f, 0.f);
#pragma unroll
    for (int t = 0; t < 8; t++) {
        a.x += pf<MODE>(X[t].x - tau, inv);
        a.y += pf<MODE>(X[t].y - tau, inv);
        a.z += pf<MODE>(X[t].z - tau, inv);
        a.w += pf<MODE>(X[t].w - tau, inv);
    }
    return (a.x + a.y) + (a.z + a.w);
}

template <int M1, int M2>
__device__ __forceinline__ void entmax_pair(
    const float* __restrict__ s1row, const float* __restrict__ s2row,
    float am1_1, float am1_2, float inv1, float inv2,
    float4* __restrict__ wrow4, float* __restrict__ wscale_slot, int s)
{
    float4 X1[8], X2[8];
    float mx1 = -3.4e38f, mx2 = -3.4e38f;
#pragma unroll
    for (int t = 0; t < 8; t++) {
        float4 v = ((const float4*)s1row)[s + 8 * t];
        v.x *= am1_1; v.y *= am1_1; v.z *= am1_1; v.w *= am1_1;
        X1[t] = v;
        mx1 = fmaxf(mx1, fmaxf(fmaxf(v.x, v.y), fmaxf(v.z, v.w)));
        float4 u = ((const float4*)s2row)[s + 8 * t];
        u.x *= am1_2; u.y *= am1_2; u.z *= am1_2; u.w *= am1_2;
        X2[t] = u;
        mx2 = fmaxf(mx2, fmaxf(fmaxf(u.x, u.y), fmaxf(u.z, u.w)));
    }
    mx1 = gmax8(mx1);
    mx2 = gmax8(mx2);

    float tau1 = mx1 - 1.f, tau2 = mx2 - 1.f;
    float dm1 = 1.f - exp2f(-8.f * am1_1);
    float dm2 = 1.f - exp2f(-8.f * am1_2);

    float flo1 = gsum8(psum32<M1>(X1, tau1, inv1)) - 1.f;
    float flo2 = gsum8(psum32<M2>(X2, tau2, inv2)) - 1.f;

    const int NBIS = (M1 == 0 || M2 == 0) ? 30 : 20;

#pragma unroll 1
    for (int it = 0; it < NBIS; it++) {
        dm1 *= 0.5f;
        dm2 *= 0.5f;
        float tm1 = tau1 + dm1;
        float tm2 = tau2 + dm2;
        float ss1 = psum32<M1>(X1, tm1, inv1);
        float ss2 = psum32<M2>(X2, tm2, inv2);
        ss1 = gsum8(ss1);
        ss2 = gsum8(ss2);
        if ((ss1 - 1.f) * flo1 >= 0.f) tau1 = tm1;
        if ((ss2 - 1.f) * flo2 >= 0.f) tau2 = tm2;
    }

    float s1 = 0.f, s2 = 0.f, s3 = 0.f;
#pragma unroll
    for (int t = 0; t < 8; t++) {
        float4 p1, p2, wf;
        p1.x = pf<M1>(X1[t].x - tau1, inv1); p2.x = pf<M2>(X2[t].x - tau2, inv2);
        p1.y = pf<M1>(X1[t].y - tau1, inv1); p2.y = pf<M2>(X2[t].y - tau2, inv2);
        p1.z = pf<M1>(X1[t].z - tau1, inv1); p2.z = pf<M2>(X2[t].z - tau2, inv2);
        p1.w = pf<M1>(X1[t].w - tau1, inv1); p2.w = pf<M2>(X2[t].w - tau2, inv2);
        wf.x = p1.x * p2.x; wf.y = p1.y * p2.y;
        wf.z = p1.z * p2.z; wf.w = p1.w * p2.w;
        s1 += (p1.x + p1.y) + (p1.z + p1.w);
        s2 += (p2.x + p2.y) + (p2.z + p2.w);
        s3 += (wf.x + wf.y) + (wf.z + wf.w);
        wrow4[s + 8 * t] = wf;
    }
    s1 = gsum8(s1);
    s2 = gsum8(s2);
    s3 = gsum8(s3);
    float scale = 1.f / (s3 + 1e-7f * s1 * s2);
    if (s == 0) *wscale_slot = scale;
}

__global__ __launch_bounds__(256, 2) void combine_kernel(
    const float* __restrict__ sem,
    const float* __restrict__ alpha1p, const float* __restrict__ alpha2p,
    float* __restrict__ out)
{
    __shared__ float4 wsm4[32][NN / 4];
    __shared__ float wscale[32];

    const int b = blockIdx.y;
    const int i0 = blockIdx.x * 32;
    const int tid = threadIdx.x;
    const int w = tid >> 5, lane = tid & 31;
    const int g = lane >> 3, s = lane & 7;
    const int rowLocal = w * 4 + g;
    const int row = i0 + rowLocal;

    const float* s1row = g_s1 + ((b * NN) + row) * NN;
    const float* s2row = g_s2 + ((b * NN) + row) * NN;

    float a1 = alpha1p[0], a2 = alpha2p[0];
    float am1_1 = a1 - 1.f, am1_2 = a2 - 1.f;
    float inv1 = 1.f / am1_1, inv2 = 1.f / am1_2;

    int m1 = (fabsf(a1 - 1.5f) < 1e-4f) ? 2 : ((fabsf(a1 - 2.f) < 1e-4f) ? 1 : 0);
    int m2 = (fabsf(a2 - 1.5f) < 1e-4f) ? 2 : ((fabsf(a2 - 2.f) < 1e-4f) ? 1 : 0);

    if (m1 == 2 && m2 == 1)
        entmax_pair<2, 1>(s1row, s2row, am1_1, am1_2, inv1, inv2,
                          wsm4[rowLocal], &wscale[rowLocal], s);
    else if (m1 == 1 && m2 == 2)
        entmax_pair<1, 2>(s1row, s2row, am1_1, am1_2, inv1, inv2,
                          wsm4[rowLocal], &wscale[rowLocal], s);
    else if (m1 == 2 && m2 == 2)
        entmax_pair<2, 2>(s1row, s2row, am1_1, am1_2, inv1, inv2,
                          wsm4[rowLocal], &wscale[rowLocal], s);
    else if (m1 == 1 && m2 == 1)
        entmax_pair<1, 1>(s1row, s2row, am1_1, am1_2, inv1, inv2,
                          wsm4[rowLocal], &wscale[rowLocal], s);
    else
        entmax_pair<0, 0>(s1row, s2row, am1_1, am1_2, inv1, inv2,
                          wsm4[rowLocal], &wscale[rowLocal], s);

    __syncthreads();

    const int d4 = tid & 31, rbase = (tid >> 5) * 4;
    ull accA[4], accB[4];
#pragma unroll
    for (int k = 0; k < 4; k++) { accA[k] = 0ull; accB[k] = 0ull; }

    const ulonglong2* semb2 = (const ulonglong2*)(sem + b * NN * DD);
    const float* wrow0 = (const float*)wsm4[rbase + 0];
    const float* wrow1 = (const float*)wsm4[rbase + 1];
    const float* wrow2 = (const float*)wsm4[rbase + 2];
    const float* wrow3 = (const float*)wsm4[rbase + 3];

#pragma unroll 4
    for (int j = 0; j < NN; j++) {
        ulonglong2 vv = semb2[j * 32 + d4];
        ull w0 = pack2(wrow0[j], wrow0[j]);
        ull w1 = pack2(wrow1[j], wrow1[j]);
        ull w2 = pack2(wrow2[j], wrow2[j]);
        ull w3 = pack2(wrow3[j], wrow3[j]);
        accA[0] = fma2(w0, vv.x, accA[0]); accB[0] = fma2(w0, vv.y, accB[0]);
        accA[1] = fma2(w1, vv.x, accA[1]); accB[1] = fma2(w1, vv.y, accB[1]);
        accA[2] = fma2(w2, vv.x, accA[2]); accB[2] = fma2(w2, vv.y, accB[2]);
        accA[3] = fma2(w3, vv.x, accA[3]); accB[3] = fma2(w3, vv.y, accB[3]);
    }

#pragma unroll
    for (int k = 0; k < 4; k++) {
        float sc = wscale[rbase + k];
        float4 o;
        unpack2(accA[k], o.x, o.y);
        unpack2(accB[k], o.z, o.w);
        o.x *= sc; o.y *= sc; o.z *= sc; o.w *= sc;
        ((float4*)(out + ((b * NN) + i0 + rbase + k) * DD))[d4] = o;
    }
}

// ---------------------------------------------------------------------------
extern "C" void kernel_launch(void* const* d_in, const int* in_sizes, int n_in,
                              void* d_out, int out_size)
{
    const float* sem  = (const float*)d_in[0];
    const float* strv = (const float*)d_in[1];
    const int*   adj  = (const int*)d_in[2];
    const float* aw   = (const float*)d_in[3];
    const float* swt  = (const float*)d_in[4];
    const float* a1   = (const float*)d_in[5];
    const float* a2   = (const float*)d_in[6];
    float* out = (float*)d_out;

    cudaFuncSetAttribute(scores_mma_kernel,
                         cudaFuncAttributeMaxDynamicSharedMemorySize, SMEMB);

    scores_mma_kernel<<<dim3(8, BB), 256, SMEMB>>>(sem, strv, adj, aw, swt);
    combine_kernel<<<dim3(NN / 32, BB), 256>>>(sem, a1, a2, out);
}